// round 7
// baseline (speedup 1.0000x reference)
#include <cuda_runtime.h>

// FeatureContraction: out[b,c,w,x,v] = sum_i x[b,c,w,x,v,i] * attr[b,c,i]
// x: [16384, 768, 16] f32, attr: [16384, 16] f32, out: [16384, 768] f32.
// Pure one-pass stream: 855 MB compulsory traffic.
// R1: float4 loads            -> 127.2 us @ 86% DRAM.
// R2: 8 bc/CTA serial loop    -> 141 us  (REGRESSION, reverted).
// R3: +ldcs/stcs hints        -> 127.0 us (NEUTRAL).
// R4: LDG.256 (v8.f32)        -> 124.8 us @ 87.6% DRAM.
// R5: hoist x loads over BAR  -> 124.8 us (kernel 122.3us, occ-invariant).
// R6: no smem/BAR, __ldg attr -> 124.9 us (NEUTRAL).
// FLOOR: kernel time == 855MB / ~6.95TB/s (path-independent LTS/DRAM cap).
// R7: 4 adjacent outputs/thread (192 thr), one STG.128 instead of 4x STG.32 —
//     4x fewer store wavefronts, cleaner DRAM write bursts.

#define BC_TOTAL 16384      // B*C
#define WXV      768        // X*Y*Y = 3*16*16
#define THREADS  192
#define PER_THR  4          // adjacent outputs per thread: 192*4 = 768

__device__ __forceinline__ void ldg256(const float* __restrict__ p,
                                       float4& lo, float4& hi)
{
    asm("ld.global.v8.f32 {%0,%1,%2,%3,%4,%5,%6,%7}, [%8];"
        : "=f"(lo.x), "=f"(lo.y), "=f"(lo.z), "=f"(lo.w),
          "=f"(hi.x), "=f"(hi.y), "=f"(hi.z), "=f"(hi.w)
        : "l"(p));
}

__device__ __forceinline__ float dot16(const float4 v[4],
                                       const float4& a0, const float4& a1,
                                       const float4& a2, const float4& a3)
{
    float s;
    s  = v[0].x * a0.x; s += v[0].y * a0.y; s += v[0].z * a0.z; s += v[0].w * a0.w;
    s += v[1].x * a1.x; s += v[1].y * a1.y; s += v[1].z * a1.z; s += v[1].w * a1.w;
    s += v[2].x * a2.x; s += v[2].y * a2.y; s += v[2].z * a2.z; s += v[2].w * a2.w;
    s += v[3].x * a3.x; s += v[3].y * a3.y; s += v[3].z * a3.z; s += v[3].w * a3.w;
    return s;
}

__global__ __launch_bounds__(THREADS)
void feature_contraction_kernel(const float* __restrict__ x,
                                const float4* __restrict__ attr,
                                float4* __restrict__ out)
{
    const int bc = blockIdx.x;

    // This thread owns 4 adjacent outputs: [o0, o0+4) within the 768.
    const int o0 = threadIdx.x * PER_THR;
    const float* __restrict__ xp = x + (size_t)bc * WXV * 16 + (size_t)o0 * 16;

    // ---- Phase 1: 8 independent LDG.256 (256B contiguous per thread). ----
    float4 v[PER_THR][4];
#pragma unroll
    for (int k = 0; k < PER_THR; k++) {
        ldg256(xp + k * 16,     v[k][0], v[k][1]);
        ldg256(xp + k * 16 + 8, v[k][2], v[k][3]);
    }

    // ---- Phase 2: attr[bc] via uniform-address broadcast (L2-resident). ----
    const float4* __restrict__ ab = attr + (size_t)bc * 4;
    const float4 a0 = __ldg(ab + 0);
    const float4 a1 = __ldg(ab + 1);
    const float4 a2 = __ldg(ab + 2);
    const float4 a3 = __ldg(ab + 3);

    // ---- Phase 3: 4 dot-16s, one vectorized STG.128. ----
    float4 r;
    r.x = dot16(v[0], a0, a1, a2, a3);
    r.y = dot16(v[1], a0, a1, a2, a3);
    r.z = dot16(v[2], a0, a1, a2, a3);
    r.w = dot16(v[3], a0, a1, a2, a3);

    out[((size_t)bc * WXV + o0) >> 2] = r;
}

extern "C" void kernel_launch(void* const* d_in, const int* in_sizes, int n_in,
                              void* d_out, int out_size)
{
    const float*  x    = (const float*)d_in[0];
    const float4* attr = (const float4*)d_in[1];
    float4*       out  = (float4*)d_out;

    feature_contraction_kernel<<<BC_TOTAL, THREADS>>>(x, attr, out);
}

// round 8
// speedup vs baseline: 1.0710x; 1.0710x over previous
#include <cuda_runtime.h>

// FeatureContraction: out[b,c,w,x,v] = sum_i x[b,c,w,x,v,i] * attr[b,c,i]
// x: [16384, 768, 16] f32, attr: [16384, 16] f32, out: [16384, 768] f32.
// Pure one-pass stream: 855 MB compulsory traffic.
//
// Session history:
// R1: float4 loads, 1 bc/CTA     -> 127.2 us @ 86% DRAM.
// R2: 8 bc/CTA serial loop       -> 141.4 us (REGRESSION: intra-CTA bubbles).
// R3: +ldcs/stcs hints           -> 127.0 us (NEUTRAL: no L2 reuse to protect).
// R4: LDG.256 (v8.f32)           -> 124.8 us @ 87.6% DRAM, L1 71->43%.
// R5: hoist x loads over BAR     -> 124.8 us (kernel 122.3us; occ-invariant).
// R6: no smem/BAR, __ldg attr    -> 124.9 us (NEUTRAL).
// R7: 4 out/thr + STG.128        -> 133.6 us (REGRESSION: regs=48 < 64 needed,
//                                   ptxas serialized the load batch, MLP lost).
// FLOOR: kernel time == 855 MB / ~6.99 TB/s — the path-independent LTS/DRAM
// cap (B300: ~6300 B/cyc, LDG.cv == TMA). FINAL = R5 structure.

#define BC_TOTAL 16384      // B*C
#define WXV      768        // X*Y*Y = 3*16*16
#define THREADS  256
#define PER_THR  (WXV / THREADS)   // 3

__device__ __forceinline__ void ldg256(const float* __restrict__ p,
                                       float4& lo, float4& hi)
{
    asm("ld.global.v8.f32 {%0,%1,%2,%3,%4,%5,%6,%7}, [%8];"
        : "=f"(lo.x), "=f"(lo.y), "=f"(lo.z), "=f"(lo.w),
          "=f"(hi.x), "=f"(hi.y), "=f"(hi.z), "=f"(hi.w)
        : "l"(p));
}

__global__ __launch_bounds__(THREADS)
void feature_contraction_kernel(const float* __restrict__ x,
                                const float4* __restrict__ attr,
                                float* __restrict__ out)
{
    const int bc = blockIdx.x;

    const float* __restrict__ xb = x + (size_t)bc * WXV * 16;

    // ---- Phase 1: issue all 6 independent LDG.256 first (true 48-reg
    // front-batch; nothing blocks them). ----
    float4 v[PER_THR][4];
    int    o[PER_THR];

#pragma unroll
    for (int k = 0; k < PER_THR; k++) {
        o[k] = k * THREADS + threadIdx.x;
        const float* __restrict__ xp = xb + (size_t)o[k] * 16;
        ldg256(xp,     v[k][0], v[k][1]);
        ldg256(xp + 8, v[k][2], v[k][3]);
    }

    // ---- Phase 2: stage attr[bc, 0:16] through smem, overlapped with the
    // x loads already in flight. ----
    __shared__ float4 s_a[4];
    if (threadIdx.x < 4) {
        s_a[threadIdx.x] = attr[(size_t)bc * 4 + threadIdx.x];
    }
    __syncthreads();

    const float4 a0 = s_a[0];
    const float4 a1 = s_a[1];
    const float4 a2 = s_a[2];
    const float4 a3 = s_a[3];

    // ---- Phase 3: FMA + store. ----
#pragma unroll
    for (int k = 0; k < PER_THR; k++) {
        float s;
        s  = v[k][0].x * a0.x;
        s += v[k][0].y * a0.y;
        s += v[k][0].z * a0.z;
        s += v[k][0].w * a0.w;
        s += v[k][1].x * a1.x;
        s += v[k][1].y * a1.y;
        s += v[k][1].z * a1.z;
        s += v[k][1].w * a1.w;
        s += v[k][2].x * a2.x;
        s += v[k][2].y * a2.y;
        s += v[k][2].z * a2.z;
        s += v[k][2].w * a2.w;
        s += v[k][3].x * a3.x;
        s += v[k][3].y * a3.y;
        s += v[k][3].z * a3.z;
        s += v[k][3].w * a3.w;
        out[(size_t)bc * WXV + o[k]] = s;
    }
}

extern "C" void kernel_launch(void* const* d_in, const int* in_sizes, int n_in,
                              void* d_out, int out_size)
{
    const float*  x    = (const float*)d_in[0];
    const float4* attr = (const float4*)d_in[1];
    float*        out  = (float*)d_out;

    feature_contraction_kernel<<<BC_TOTAL, THREADS>>>(x, attr, out);
}

// round 9
// speedup vs baseline: 1.0805x; 1.0088x over previous
#include <cuda_runtime.h>

// FeatureContraction: out[b,c,w,x,v] = sum_i x[b,c,w,x,v,i] * attr[b,c,i]
// x: [16384, 768, 16] f32, attr: [16384, 16] f32, out: [16384, 768] f32.
// Pure one-pass stream: 855 MB compulsory traffic.
//
// Session history:
// R1: float4 loads, 1 bc/CTA     -> 127.2 us @ 86% DRAM.
// R2: 8 bc/CTA SERIAL loop       -> 141.4 us (REGRESSION: dependency bubbles).
// R3: +ldcs/stcs hints           -> 127.0 us (NEUTRAL).
// R4: LDG.256 (v8.f32)           -> 124.8 us @ 87.6% DRAM, L1 71->43%.
// R5: hoist x loads over BAR     -> 124.8 us (kernel 122.3us; occ-invariant).
// R6: no smem/BAR, __ldg attr    -> 124.9 us (NEUTRAL).
// R7: 4 out/thr + STG.128        -> 133.6 us (REGRESSION: load batch serialized).
// R8: R5 confirmed               -> 124.77 us, kernel 121.9us @ 88.5% DRAM,
//                                   7009 GB/s == 855MB/121.9us. FLOOR.
// R9: PARALLEL 2-bc merge: 512 threads, 2 bc/CTA side-by-side. Per-thread
//     load shape unchanged (6 front-batched LDG.256); halves CTA count to
//     probe wave-transition slack. Expect neutral-to-tiny-gain.

#define BC_TOTAL   16384      // B*C
#define WXV        768        // X*Y*Y = 3*16*16
#define BC_PER_BLK 2
#define THREADS    (256 * BC_PER_BLK)       // 512
#define PER_THR    3                         // outputs per thread
#define GRID       (BC_TOTAL / BC_PER_BLK)   // 8192

__device__ __forceinline__ void ldg256(const float* __restrict__ p,
                                       float4& lo, float4& hi)
{
    asm("ld.global.v8.f32 {%0,%1,%2,%3,%4,%5,%6,%7}, [%8];"
        : "=f"(lo.x), "=f"(lo.y), "=f"(lo.z), "=f"(lo.w),
          "=f"(hi.x), "=f"(hi.y), "=f"(hi.z), "=f"(hi.w)
        : "l"(p));
}

__global__ __launch_bounds__(THREADS)
void feature_contraction_kernel(const float* __restrict__ x,
                                const float4* __restrict__ attr,
                                float* __restrict__ out)
{
    // Threads [0,256) handle bc0, threads [256,512) handle bc0+1.
    const int sub  = threadIdx.x >> 8;          // 0 or 1
    const int tid  = threadIdx.x & 255;         // 0..255 within sub-block
    const int bc   = blockIdx.x * BC_PER_BLK + sub;

    const float* __restrict__ xb = x + (size_t)bc * WXV * 16;

    // ---- Phase 1: issue all 6 independent LDG.256 first. ----
    float4 v[PER_THR][4];
    int    o[PER_THR];

#pragma unroll
    for (int k = 0; k < PER_THR; k++) {
        o[k] = k * 256 + tid;
        const float* __restrict__ xp = xb + (size_t)o[k] * 16;
        ldg256(xp,     v[k][0], v[k][1]);
        ldg256(xp + 8, v[k][2], v[k][3]);
    }

    // ---- Phase 2: stage both bc's attr vectors through smem, overlapped
    // with the x loads in flight. s_a[sub][0..3]. ----
    __shared__ float4 s_a[BC_PER_BLK][4];
    if (threadIdx.x < 4 * BC_PER_BLK) {
        const int j = threadIdx.x >> 2;          // which bc
        const int q = threadIdx.x & 3;           // which float4
        s_a[j][q] = attr[((size_t)blockIdx.x * BC_PER_BLK + j) * 4 + q];
    }
    __syncthreads();

    const float4 a0 = s_a[sub][0];
    const float4 a1 = s_a[sub][1];
    const float4 a2 = s_a[sub][2];
    const float4 a3 = s_a[sub][3];

    // ---- Phase 3: FMA + store. ----
#pragma unroll
    for (int k = 0; k < PER_THR; k++) {
        float s;
        s  = v[k][0].x * a0.x;
        s += v[k][0].y * a0.y;
        s += v[k][0].z * a0.z;
        s += v[k][0].w * a0.w;
        s += v[k][1].x * a1.x;
        s += v[k][1].y * a1.y;
        s += v[k][1].z * a1.z;
        s += v[k][1].w * a1.w;
        s += v[k][2].x * a2.x;
        s += v[k][2].y * a2.y;
        s += v[k][2].z * a2.z;
        s += v[k][2].w * a2.w;
        s += v[k][3].x * a3.x;
        s += v[k][3].y * a3.y;
        s += v[k][3].z * a3.z;
        s += v[k][3].w * a3.w;
        out[(size_t)bc * WXV + o[k]] = s;
    }
}

extern "C" void kernel_launch(void* const* d_in, const int* in_sizes, int n_in,
                              void* d_out, int out_size)
{
    const float*  x    = (const float*)d_in[0];
    const float4* attr = (const float4*)d_in[1];
    float*        out  = (float*)d_out;

    feature_contraction_kernel<<<GRID, THREADS>>>(x, attr, out);
}